// round 1
// baseline (speedup 1.0000x reference)
#include <cuda_runtime.h>
#include <cuda_bf16.h>
#include <math.h>

// Problem constants
#define BATCH 2
#define TT 2048
#define MM 512
#define CC 512
#define HH 8
#define DD 64
#define SCALE 0.125f   // 1/sqrt(64)

// ---------------- scratch (device globals; no allocation allowed) -------------
__device__ float g_qkv_x[(long)BATCH*TT*3*CC];        // [4096,1536]
__device__ float g_qkv_y[(long)BATCH*MM*3*CC];        // [1024,1536]
__device__ float g_catt_x2y[(long)BATCH*HH*TT*MM];    // [B,H,T,M] raw scores
__device__ float g_p_x2y[(long)BATCH*HH*TT*MM];       // softmax of above
__device__ float g_catt_y2x[(long)BATCH*HH*MM*TT];    // [B,H,M,T]
__device__ float g_big[(long)BATCH*HH*TT*TT];         // [B,H,T,T] prod / satt (reused)
__device__ float g_cval[(long)BATCH*TT*CC];
__device__ float g_sval[(long)BATCH*TT*CC];
__device__ float g_t1[(long)BATCH*TT*CC];
__device__ float g_t2[(long)BATCH*TT*CC];
__device__ float g_t3[(long)BATCH*TT*CC];

// ---------------- generic tiled fp32 GEMM ------------------------------------
// C[i,j] = alpha * sum_k A[i,k] * op(B)[k,j]  (+ bias[j])  (+= if ACC)
// Batched over blockIdx.z with z = b*Hn + h; per-matrix offset = b*s?b + h*s?h.
#define BM 64
#define BN 64
#define BK 16
#define LDS 68   // padded smem row stride (floats); 68*4B = 272B = 17*16B (16B aligned)

template<bool TB, bool ACC, bool BIAS>
__global__ void __launch_bounds__(256) gemm_k(
    const float* __restrict__ A, const float* __restrict__ Bm,
    float* __restrict__ C, const float* __restrict__ bias,
    int Mg, int Ng, int Kg, int lda, int ldb, int ldc,
    long sAb, long sAh, long sBb, long sBh, long sCb, long sCh,
    int Hn, float alpha)
{
    int z = blockIdx.z;
    int bb = z / Hn, hh = z - bb * Hn;
    A  += (long)bb * sAb + (long)hh * sAh;
    Bm += (long)bb * sBb + (long)hh * sBh;
    C  += (long)bb * sCb + (long)hh * sCh;

    __shared__ __align__(16) float As[BK][LDS];
    __shared__ __align__(16) float Bs[BK][LDS];

    int tid = threadIdx.x;
    int tx = tid & 15, ty = tid >> 4;
    int m0 = blockIdx.y * BM, n0 = blockIdx.x * BN;

    float acc[4][4] = {};

    for (int k0 = 0; k0 < Kg; k0 += BK) {
        // load A tile: 64 rows x 16 k  (16 threads per row, coalesced 64B/row)
        #pragma unroll
        for (int l = 0; l < 4; ++l) {
            int idx = tid + l * 256;
            int r = idx >> 4, kk = idx & 15;
            As[kk][r] = A[(long)(m0 + r) * lda + (k0 + kk)];
        }
        if (TB) {
            #pragma unroll
            for (int l = 0; l < 4; ++l) {
                int idx = tid + l * 256;
                int c = idx >> 4, kk = idx & 15;
                Bs[kk][c] = Bm[(long)(n0 + c) * ldb + (k0 + kk)];
            }
        } else {
            #pragma unroll
            for (int l = 0; l < 4; ++l) {
                int idx = tid + l * 256;
                int kk = idx >> 6, c = idx & 63;
                Bs[kk][c] = Bm[(long)(k0 + kk) * ldb + (n0 + c)];
            }
        }
        __syncthreads();

        #pragma unroll
        for (int kk = 0; kk < BK; ++kk) {
            float4 a4 = *(const float4*)&As[kk][ty * 4];
            float4 b4 = *(const float4*)&Bs[kk][tx * 4];
            float av[4] = {a4.x, a4.y, a4.z, a4.w};
            float bv[4] = {b4.x, b4.y, b4.z, b4.w};
            #pragma unroll
            for (int i = 0; i < 4; ++i)
                #pragma unroll
                for (int j = 0; j < 4; ++j)
                    acc[i][j] += av[i] * bv[j];
        }
        __syncthreads();
    }

    #pragma unroll
    for (int i = 0; i < 4; ++i) {
        int r = m0 + ty * 4 + i;
        #pragma unroll
        for (int j = 0; j < 4; ++j) {
            int cc = n0 + tx * 4 + j;
            float v = alpha * acc[i][j];
            if (BIAS) v += bias[cc];
            long off = (long)r * ldc + cc;
            if (ACC) C[off] += v; else C[off] = v;
        }
    }
}

// ---------------- row softmax (optional int mask; mask==0 -> excluded) --------
__global__ void __launch_bounds__(256) softmax_k(
    const float* __restrict__ in, float* __restrict__ out,
    const int* __restrict__ mask, int len, int maskld)
{
    int t = blockIdx.x;
    long rowoff = ((long)blockIdx.y * gridDim.x + t) * (long)len;
    const float* r = in + rowoff;
    float* o = out + rowoff;
    const int* mr = mask ? (mask + (long)t * maskld) : nullptr;

    __shared__ float sd[256];
    int tid = threadIdx.x;

    float m = -INFINITY;
    for (int i = tid; i < len; i += 256) {
        if (mr && mr[i] == 0) continue;
        m = fmaxf(m, r[i]);
    }
    sd[tid] = m; __syncthreads();
    for (int s = 128; s > 0; s >>= 1) {
        if (tid < s) sd[tid] = fmaxf(sd[tid], sd[tid + s]);
        __syncthreads();
    }
    m = sd[0];
    __syncthreads();

    float sum = 0.0f;
    for (int i = tid; i < len; i += 256) {
        if (mr && mr[i] == 0) continue;
        sum += __expf(r[i] - m);
    }
    sd[tid] = sum; __syncthreads();
    for (int s = 128; s > 0; s >>= 1) {
        if (tid < s) sd[tid] += sd[tid + s];
        __syncthreads();
    }
    float inv = 1.0f / sd[0];

    for (int i = tid; i < len; i += 256) {
        float v = (mr && mr[i] == 0) ? 0.0f : __expf(r[i] - m) * inv;
        o[i] = v;
    }
}

// ---------------- gate combine: t3 = sig(t1)*cval + sig(t2)*sval --------------
__global__ void __launch_bounds__(256) gate_combine_k(
    const float* __restrict__ gs, const float* __restrict__ gc,
    const float* __restrict__ cval, const float* __restrict__ sval,
    float* __restrict__ outv, int n)
{
    int i = blockIdx.x * 256 + threadIdx.x;
    if (i < n) {
        float a = 1.0f / (1.0f + __expf(-gs[i]));
        float b = 1.0f / (1.0f + __expf(-gc[i]));
        outv[i] = a * cval[i] + b * sval[i];
    }
}

// ------------------------------------------------------------------------------
extern "C" void kernel_launch(void* const* d_in, const int* in_sizes, int n_in,
                              void* d_out, int out_size)
{
    const float* x       = (const float*)d_in[0];   // [2,2048,512]
    const float* y       = (const float*)d_in[1];   // [2,512,512]
    const int*   mask    = (const int*)  d_in[2];   // [1,1,2048,2048]
    const float* Wqkv_x  = (const float*)d_in[3];   // [512,1536]
    const float* bqkv_x  = (const float*)d_in[4];
    const float* Wqkv_y  = (const float*)d_in[5];
    const float* bqkv_y  = (const float*)d_in[6];
    const float* Wgs     = (const float*)d_in[7];
    const float* bgs     = (const float*)d_in[8];
    const float* Wgc     = (const float*)d_in[9];
    const float* bgc     = (const float*)d_in[10];
    const float* Wp      = (const float*)d_in[11];
    const float* bp      = (const float*)d_in[12];
    float* out = (float*)d_out;

    float *qkvx, *qkvy, *cx2y, *px2y, *cy2x, *big, *cval, *sval, *t1, *t2, *t3;
    cudaGetSymbolAddress((void**)&qkvx, g_qkv_x);
    cudaGetSymbolAddress((void**)&qkvy, g_qkv_y);
    cudaGetSymbolAddress((void**)&cx2y, g_catt_x2y);
    cudaGetSymbolAddress((void**)&px2y, g_p_x2y);
    cudaGetSymbolAddress((void**)&cy2x, g_catt_y2x);
    cudaGetSymbolAddress((void**)&big,  g_big);
    cudaGetSymbolAddress((void**)&cval, g_cval);
    cudaGetSymbolAddress((void**)&sval, g_sval);
    cudaGetSymbolAddress((void**)&t1,   g_t1);
    cudaGetSymbolAddress((void**)&t2,   g_t2);
    cudaGetSymbolAddress((void**)&t3,   g_t3);

    dim3 blk(256);
    const int BH = BATCH * HH;

    // 1) qkv_x = x @ Wqkv_x + b   [4096,1536]
    gemm_k<false,false,true><<<dim3(3*CC/BN, BATCH*TT/BM, 1), blk>>>(
        x, Wqkv_x, qkvx, bqkv_x, BATCH*TT, 3*CC, CC,
        CC, 3*CC, 3*CC, 0,0,0,0,0,0, 1, 1.0f);

    // 2) qkv_y = y @ Wqkv_y + b   [1024,1536]
    gemm_k<false,false,true><<<dim3(3*CC/BN, BATCH*MM/BM, 1), blk>>>(
        y, Wqkv_y, qkvy, bqkv_y, BATCH*MM, 3*CC, CC,
        CC, 3*CC, 3*CC, 0,0,0,0,0,0, 1, 1.0f);

    // 3) catt_x2y[b,h] = q_x @ k_y^T * SCALE   [T,M], K=64
    gemm_k<true,false,false><<<dim3(MM/BN, TT/BM, BH), blk>>>(
        qkvx, qkvy + CC, cx2y, nullptr, TT, MM, DD,
        3*CC, 3*CC, MM,
        (long)TT*3*CC, DD, (long)MM*3*CC, DD,
        (long)HH*TT*MM, (long)TT*MM, HH, SCALE);

    // 4) catt_y2x[b,h] = q_y @ k_x^T * SCALE   [M,T], K=64
    gemm_k<true,false,false><<<dim3(TT/BN, MM/BM, BH), blk>>>(
        qkvy, qkvx + CC, cy2x, nullptr, MM, TT, DD,
        3*CC, 3*CC, TT,
        (long)MM*3*CC, DD, (long)TT*3*CC, DD,
        (long)HH*MM*TT, (long)MM*TT, HH, SCALE);

    // 5) p_x2y = softmax(catt_x2y) over M
    softmax_k<<<dim3(TT, BH), blk>>>(cx2y, px2y, nullptr, MM, 0);

    // 6) cval = p_x2y @ v_y   [T,64], K=512
    gemm_k<false,false,false><<<dim3(DD/BN, TT/BM, BH), blk>>>(
        px2y, qkvy + 2*CC, cval, nullptr, TT, DD, MM,
        MM, 3*CC, CC,
        (long)HH*TT*MM, (long)TT*MM, (long)MM*3*CC, DD,
        (long)TT*CC, DD, HH, 1.0f);

    // 7) prod = catt_x2y @ catt_y2x * SCALE   [T,T], K=512  (dominant GEMM)
    gemm_k<false,false,false><<<dim3(TT/BN, TT/BM, BH), blk>>>(
        cx2y, cy2x, big, nullptr, TT, TT, MM,
        MM, TT, TT,
        (long)HH*TT*MM, (long)TT*MM, (long)HH*MM*TT, (long)MM*TT,
        (long)HH*TT*TT, (long)TT*TT, HH, SCALE);

    // 8) masked softmax of prod (in place)
    softmax_k<<<dim3(TT, BH), blk>>>(big, big, mask, TT, TT);

    // 9) cval += softmax(prod) @ v_x   [T,64], K=2048
    gemm_k<false,true,false><<<dim3(DD/BN, TT/BM, BH), blk>>>(
        big, qkvx + 2*CC, cval, nullptr, TT, DD, TT,
        TT, 3*CC, CC,
        (long)HH*TT*TT, (long)TT*TT, (long)TT*3*CC, DD,
        (long)TT*CC, DD, HH, 1.0f);

    // 10) satt = q_x @ k_x^T * SCALE  [T,T], K=64  (into big, reused)
    gemm_k<true,false,false><<<dim3(TT/BN, TT/BM, BH), blk>>>(
        qkvx, qkvx + CC, big, nullptr, TT, TT, DD,
        3*CC, 3*CC, TT,
        (long)TT*3*CC, DD, (long)TT*3*CC, DD,
        (long)HH*TT*TT, (long)TT*TT, HH, SCALE);

    // 11) masked softmax (in place)
    softmax_k<<<dim3(TT, BH), blk>>>(big, big, mask, TT, TT);

    // 12) sval = softmax(satt) @ v_x
    gemm_k<false,false,false><<<dim3(DD/BN, TT/BM, BH), blk>>>(
        big, qkvx + 2*CC, sval, nullptr, TT, DD, TT,
        TT, 3*CC, CC,
        (long)HH*TT*TT, (long)TT*TT, (long)TT*3*CC, DD,
        (long)TT*CC, DD, HH, 1.0f);

    // 13) t1 = sval @ Wgs + bgs
    gemm_k<false,false,true><<<dim3(CC/BN, BATCH*TT/BM, 1), blk>>>(
        sval, Wgs, t1, bgs, BATCH*TT, CC, CC,
        CC, CC, CC, 0,0,0,0,0,0, 1, 1.0f);

    // 14) t2 = cval @ Wgc + bgc
    gemm_k<false,false,true><<<dim3(CC/BN, BATCH*TT/BM, 1), blk>>>(
        cval, Wgc, t2, bgc, BATCH*TT, CC, CC,
        CC, CC, CC, 0,0,0,0,0,0, 1, 1.0f);

    // 15) t3 = sigmoid(t1)*cval + sigmoid(t2)*sval
    {
        int n = BATCH * TT * CC;
        gate_combine_k<<<(n + 255) / 256, blk>>>(t1, t2, cval, sval, t3, n);
    }

    // 16) out = t3 @ Wp + bp
    gemm_k<false,false,true><<<dim3(CC/BN, BATCH*TT/BM, 1), blk>>>(
        t3, Wp, out, bp, BATCH*TT, CC, CC,
        CC, CC, CC, 0,0,0,0,0,0, 1, 1.0f);
}